// round 1
// baseline (speedup 1.0000x reference)
#include <cuda_runtime.h>
#include <math.h>

#define MDIM 128        // N_COMBOS (rows of S, dual dim)
#define NDIM 512        // N_STRUCTS (cols of S, primal dim)
#define HID  20
#define NITER 60
#define CONTROLF 10.0f
#define RCAP 64         // max nnz per row of S (mean ~16)
#define CCAP 24         // max nnz per col of S (mean ~4)

// Scratch (no allocations allowed)
__device__ int            g_csr_cnt[MDIM];
__device__ unsigned short g_csr_idx[MDIM * RCAP];
__device__ int            g_csc_cnt[NDIM];
__device__ unsigned char  g_csc_idx[NDIM * CCAP];
__device__ float          g_tau;

// ---------------------------------------------------------------------------
// Kernel 0: build CSR/CSC for S, then 30-step power iteration for the
// spectral bound L = sqrt(lambda_max(S^T S + I)); tau = sig = 0.9/L.
// One block, 512 threads.
// ---------------------------------------------------------------------------
__global__ void prep_kernel(const float* __restrict__ S) {
    const int t = threadIdx.x;  // 0..511

    // CSC: thread t scans column t (coalesced across threads)
    {
        int cnt = 0;
        for (int m = 0; m < MDIM; m++) {
            if (S[m * NDIM + t] != 0.0f) {
                if (cnt < CCAP) g_csc_idx[t * CCAP + cnt] = (unsigned char)m;
                cnt++;
            }
        }
        g_csc_cnt[t] = cnt < CCAP ? cnt : CCAP;
    }
    // CSR: threads 0..127 scan their row
    if (t < MDIM) {
        int cnt = 0;
        for (int n = 0; n < NDIM; n++) {
            if (S[t * NDIM + n] != 0.0f) {
                if (cnt < RCAP) g_csr_idx[t * RCAP + cnt] = (unsigned short)n;
                cnt++;
            }
        }
        g_csr_cnt[t] = cnt < RCAP ? cnt : RCAP;
    }
    __syncthreads();

    __shared__ float v[NDIM];
    __shared__ float p[MDIM];
    __shared__ float red[16];

    v[t] = 1.0f;
    __syncthreads();

    const int ccnt = g_csc_cnt[t];
    float Lsq = 0.0f;

    for (int it = 0; it <= 30; it++) {
        // p = S v (sparse rows)
        if (t < MDIM) {
            float a = 0.0f;
            const int rc = g_csr_cnt[t];
            for (int j = 0; j < rc; j++) a += v[g_csr_idx[t * RCAP + j]];
            p[t] = a;
        }
        __syncthreads();
        // u = S^T p + v (sparse cols)
        float a = v[t];
        for (int j = 0; j < ccnt; j++) a += p[g_csc_idx[t * CCAP + j]];

        float s = (it == 30) ? (a * v[t]) : (a * a);
        #pragma unroll
        for (int o = 16; o > 0; o >>= 1) s += __shfl_xor_sync(0xffffffffu, s, o);
        if ((t & 31) == 0) red[t >> 5] = s;
        __syncthreads();
        float tot = 0.0f;
        #pragma unroll
        for (int w = 0; w < 16; w++) tot += red[w];

        if (it == 30) { Lsq = tot; break; }

        v[t] = a / sqrtf(tot);     // v = u / ||u||
        __syncthreads();
    }

    if (t == 0) g_tau = 0.9f / sqrtf(Lsq);
}

// ---------------------------------------------------------------------------
// Kernel 1: fused MLP + 60-iteration PDHG. One CTA per batch row, 128 threads.
// Thread t owns primal elements n = t + 128*k, k in 0..3, and dual element t.
// ---------------------------------------------------------------------------
__global__ void __launch_bounds__(128, 16) solve_kernel(
    const float* __restrict__ X,
    const float* __restrict__ W1, const float* __restrict__ B1,
    const float* __restrict__ W2, const float* __restrict__ B2,
    const float* __restrict__ W3, const float* __restrict__ B3,
    const float* __restrict__ W4, const float* __restrict__ B4,
    float* __restrict__ out)
{
    const int row = blockIdx.x;
    const int t   = threadIdx.x;   // 0..127

    __shared__ float bx[MDIM];       // Xf row (also the LP rhs b)
    __shared__ float xb_sh[NDIM];
    __shared__ float lam1_sh[MDIM];
    __shared__ float h[HID];
    __shared__ float red[4];

    bx[t] = X[row * MDIM + t];
    __syncthreads();

    // ---- MLP: z = W4^T tanh(W3^T tanh(W2^T tanh(W1^T xf))) + biases ----
    if (t < HID) {
        float a = B1[t];
        for (int k = 0; k < MDIM; k++) a += bx[k] * W1[k * HID + t];
        h[t] = tanhf(a);
    }
    __syncthreads();
    {
        float a = 0.0f;
        if (t < HID) {
            a = B2[t];
            #pragma unroll
            for (int k = 0; k < HID; k++) a += h[k] * W2[k * HID + t];
            a = tanhf(a);
        }
        __syncthreads();
        if (t < HID) h[t] = a;
        __syncthreads();
        if (t < HID) {
            a = B3[t];
            #pragma unroll
            for (int k = 0; k < HID; k++) a += h[k] * W3[k * HID + t];
            a = tanhf(a);
        }
        __syncthreads();
        if (t < HID) h[t] = a;
        __syncthreads();
    }

    float z[4], x[4], lam2[4];
    #pragma unroll
    for (int k = 0; k < 4; k++) {
        const int n = t + 128 * k;
        float a = B4[n];
        #pragma unroll
        for (int j = 0; j < HID; j++) a += h[j] * W4[j * NDIM + n];
        z[k] = a;
        x[k] = fmaxf(a, 0.0f);
        lam2[k] = 0.0f;
        xb_sh[n] = x[k];
    }
    lam1_sh[t] = 0.0f;

    const float tau = g_tau;          // sig == tau
    const int   rcnt = g_csr_cnt[t];
    const int   cc0 = g_csc_cnt[t];
    const int   cc1 = g_csc_cnt[t + 128];
    const int   cc2 = g_csc_cnt[t + 256];
    const int   cc3 = g_csc_cnt[t + 384];
    __syncthreads();

    // ---- PDHG mainloop ----
    for (int it = 0; it < NITER; it++) {
        // dual 1: u1[m] = lam1[m] + sig * (S xb)[m]; lam1 = max(u1 - sig*b, 0)
        float acc = 0.0f;
        for (int j = 0; j < rcnt; j++) acc += xb_sh[g_csr_idx[t * RCAP + j]];
        const float nl1 = fmaxf(lam1_sh[t] + tau * acc - tau * bx[t], 0.0f);

        // dual 2 (elementwise): lam2 = min(lam2 + sig*xb, 0)
        #pragma unroll
        for (int k = 0; k < 4; k++)
            lam2[k] = fminf(lam2[k] + tau * xb_sh[t + 128 * k], 0.0f);

        lam1_sh[t] = nl1;           // own slot; prior cross-reads fenced by loop-end sync
        __syncthreads();

        // primal: v = x - tau*(S^T lam1 + lam2); u = v + tau - z
        float u[4];
        float ss = 0.0f;
        {
            float ca;
            ca = 0.0f; for (int j = 0; j < cc0; j++) ca += lam1_sh[g_csc_idx[(t      ) * CCAP + j]];
            u[0] = (x[0] - tau * (ca + lam2[0])) + tau - z[0];
            ca = 0.0f; for (int j = 0; j < cc1; j++) ca += lam1_sh[g_csc_idx[(t + 128) * CCAP + j]];
            u[1] = (x[1] - tau * (ca + lam2[1])) + tau - z[1];
            ca = 0.0f; for (int j = 0; j < cc2; j++) ca += lam1_sh[g_csc_idx[(t + 256) * CCAP + j]];
            u[2] = (x[2] - tau * (ca + lam2[2])) + tau - z[2];
            ca = 0.0f; for (int j = 0; j < cc3; j++) ca += lam1_sh[g_csc_idx[(t + 384) * CCAP + j]];
            u[3] = (x[3] - tau * (ca + lam2[3])) + tau - z[3];
        }
        #pragma unroll
        for (int k = 0; k < 4; k++) ss += u[k] * u[k];

        // block reduce ||u||^2 over 512 elements (4 warps)
        #pragma unroll
        for (int o = 16; o > 0; o >>= 1) ss += __shfl_xor_sync(0xffffffffu, ss, o);
        if ((t & 31) == 0) red[t >> 5] = ss;
        __syncthreads();
        const float nrm = sqrtf(red[0] + red[1] + red[2] + red[3]);
        const float scale = fmaxf(0.0f, 1.0f - tau * CONTROLF / fmaxf(nrm, 1e-12f));

        #pragma unroll
        for (int k = 0; k < 4; k++) {
            const float xn = z[k] + scale * u[k];
            xb_sh[t + 128 * k] = 2.0f * xn - x[k];
            x[k] = xn;
        }
        __syncthreads();
    }

    #pragma unroll
    for (int k = 0; k < 4; k++)
        out[row * NDIM + t + 128 * k] = x[k];
}

// ---------------------------------------------------------------------------
extern "C" void kernel_launch(void* const* d_in, const int* in_sizes, int n_in,
                              void* d_out, int out_size) {
    const float* X  = (const float*)d_in[0];
    const float* W1 = (const float*)d_in[1];
    const float* B1 = (const float*)d_in[2];
    const float* W2 = (const float*)d_in[3];
    const float* B2 = (const float*)d_in[4];
    const float* W3 = (const float*)d_in[5];
    const float* B3 = (const float*)d_in[6];
    const float* W4 = (const float*)d_in[7];
    const float* B4 = (const float*)d_in[8];
    const float* S  = (const float*)d_in[9];
    const int batch = in_sizes[0] / MDIM;

    prep_kernel<<<1, NDIM>>>(S);
    solve_kernel<<<batch, MDIM>>>(X, W1, B1, W2, B2, W3, B3, W4, B4,
                                  (float*)d_out);
}

// round 2
// speedup vs baseline: 5.7105x; 5.7105x over previous
#include <cuda_runtime.h>
#include <math.h>

#define MDIM 128        // N_COMBOS (dual dim)
#define NDIM 512        // N_STRUCTS (primal dim)
#define HID  20
#define NITER 60
#define CONTROLF 10.0f
#define RCAP 64         // max nnz per row of S (mean ~16)
#define CCAP 24         // max nnz per col of S (mean ~4)
#define RROWS 4         // batch rows per CTA

// Scratch (no allocations allowed). Index arrays are TRANSPOSED so that the
// per-iteration index loads are coalesced across threads.
__device__ int            g_csr_cnt[MDIM];
__device__ unsigned short g_csr_idxT[RCAP * MDIM];   // [j][m]
__device__ int            g_csc_cnt[NDIM];
__device__ unsigned char  g_csc_idxT[CCAP * NDIM];   // [j][n]
__device__ float          g_tau;

// ---------------------------------------------------------------------------
// Kernel 0: build transposed CSR/CSC for S, then 30-step power iteration for
// L = sqrt(lambda_max(S^T S + I)); tau = sig = 0.9/L. One block, 512 threads.
// ---------------------------------------------------------------------------
__global__ void prep_kernel(const float* __restrict__ S) {
    const int t = threadIdx.x;  // 0..511

    // CSC: thread t scans column t (coalesced across threads)
    {
        int cnt = 0;
        for (int m = 0; m < MDIM; m++) {
            if (S[m * NDIM + t] != 0.0f) {
                if (cnt < CCAP) g_csc_idxT[cnt * NDIM + t] = (unsigned char)m;
                cnt++;
            }
        }
        g_csc_cnt[t] = cnt < CCAP ? cnt : CCAP;
    }
    // CSR: threads 0..127 scan their row
    if (t < MDIM) {
        int cnt = 0;
        for (int n = 0; n < NDIM; n++) {
            if (S[t * NDIM + n] != 0.0f) {
                if (cnt < RCAP) g_csr_idxT[cnt * MDIM + t] = (unsigned short)n;
                cnt++;
            }
        }
        g_csr_cnt[t] = cnt < RCAP ? cnt : RCAP;
    }
    __syncthreads();

    __shared__ float v[NDIM];
    __shared__ float p[MDIM];
    __shared__ float red[16];

    v[t] = 1.0f;
    __syncthreads();

    const int ccnt = g_csc_cnt[t];
    float Lsq = 0.0f;

    for (int it = 0; it <= 30; it++) {
        // p = S v (sparse rows)
        if (t < MDIM) {
            float a = 0.0f;
            const int rc = g_csr_cnt[t];
            for (int j = 0; j < rc; j++) a += v[g_csr_idxT[j * MDIM + t]];
            p[t] = a;
        }
        __syncthreads();
        // u = S^T p + v (sparse cols)
        float a = v[t];
        for (int j = 0; j < ccnt; j++) a += p[g_csc_idxT[j * NDIM + t]];

        float s = (it == 30) ? (a * v[t]) : (a * a);
        #pragma unroll
        for (int o = 16; o > 0; o >>= 1) s += __shfl_xor_sync(0xffffffffu, s, o);
        if ((t & 31) == 0) red[t >> 5] = s;
        __syncthreads();
        float tot = 0.0f;
        #pragma unroll
        for (int w = 0; w < 16; w++) tot += red[w];

        if (it == 30) { Lsq = tot; break; }

        v[t] = a / sqrtf(tot);
        __syncthreads();
    }

    if (t == 0) g_tau = 0.9f / sqrtf(Lsq);
}

// ---------------------------------------------------------------------------
// float4 helpers
// ---------------------------------------------------------------------------
__device__ __forceinline__ float4 f4add(float4 a, float4 b) {
    return make_float4(a.x + b.x, a.y + b.y, a.z + b.z, a.w + b.w);
}

// ---------------------------------------------------------------------------
// Kernel 1: fused MLP + 60-iteration PDHG, 4 batch rows per CTA, 128 threads.
// Shared per-element state is float4 (one lane per batch row) so that each
// random gather LDS.128 serves all 4 rows.
// ---------------------------------------------------------------------------
__global__ void __launch_bounds__(128) solve_kernel(
    const float* __restrict__ X,
    const float* __restrict__ W1, const float* __restrict__ B1,
    const float* __restrict__ W2, const float* __restrict__ B2,
    const float* __restrict__ W3, const float* __restrict__ B3,
    const float* __restrict__ W4, const float* __restrict__ B4,
    float* __restrict__ out)
{
    const int row0 = blockIdx.x * RROWS;
    const int t    = threadIdx.x;   // 0..127

    __shared__ float4 bx_sh[MDIM];      // Xf rows (LP rhs), 4 rows per slot
    __shared__ float4 xb_sh[NDIM];
    __shared__ float4 lam1_sh[MDIM];
    __shared__ float  h_sh[RROWS][HID + 4];
    __shared__ float4 red[4];

    {
        float4 v;
        v.x = X[(row0 + 0) * MDIM + t];
        v.y = X[(row0 + 1) * MDIM + t];
        v.z = X[(row0 + 2) * MDIM + t];
        v.w = X[(row0 + 3) * MDIM + t];
        bx_sh[t] = v;
    }
    __syncthreads();

    // ---- MLP (4 rows in parallel; threads 0..79 = (row r, unit i)) ----
    if (t < RROWS * HID) {
        const int r = t / HID, i = t % HID;
        float a = B1[i];
        for (int k = 0; k < MDIM; k++)
            a += ((const float*)&bx_sh[k])[r] * W1[k * HID + i];
        h_sh[r][i] = tanhf(a);
    }
    __syncthreads();
    {
        float a = 0.0f;
        if (t < RROWS * HID) {
            const int r = t / HID, i = t % HID;
            a = B2[i];
            #pragma unroll
            for (int k = 0; k < HID; k++) a += h_sh[r][k] * W2[k * HID + i];
            a = tanhf(a);
        }
        __syncthreads();
        if (t < RROWS * HID) h_sh[t / HID][t % HID] = a;
        __syncthreads();
        if (t < RROWS * HID) {
            const int r = t / HID, i = t % HID;
            a = B3[i];
            #pragma unroll
            for (int k = 0; k < HID; k++) a += h_sh[r][k] * W3[k * HID + i];
            a = tanhf(a);
        }
        __syncthreads();
        if (t < RROWS * HID) h_sh[t / HID][t % HID] = a;
        __syncthreads();
    }

    float4 z[4], x[4], lam2[4], xb[4];
    #pragma unroll
    for (int k = 0; k < 4; k++) {
        const int n = t + 128 * k;
        const float b4v = B4[n];
        float4 a = make_float4(b4v, b4v, b4v, b4v);
        #pragma unroll
        for (int j = 0; j < HID; j++) {
            const float w = W4[j * NDIM + n];
            a.x += h_sh[0][j] * w;
            a.y += h_sh[1][j] * w;
            a.z += h_sh[2][j] * w;
            a.w += h_sh[3][j] * w;
        }
        z[k] = a;
        x[k] = make_float4(fmaxf(a.x, 0.f), fmaxf(a.y, 0.f),
                           fmaxf(a.z, 0.f), fmaxf(a.w, 0.f));
        lam2[k] = make_float4(0.f, 0.f, 0.f, 0.f);
        xb[k] = x[k];
        xb_sh[n] = x[k];
    }

    float4 lam1r = make_float4(0.f, 0.f, 0.f, 0.f);
    lam1_sh[t] = lam1r;
    const float4 b4 = bx_sh[t];
    const float tau = g_tau;                  // sig == tau
    const int rcnt = g_csr_cnt[t];
    int cc[4];
    #pragma unroll
    for (int k = 0; k < 4; k++) cc[k] = g_csc_cnt[t + 128 * k];
    __syncthreads();

    // ---- PDHG mainloop ----
    for (int it = 0; it < NITER; it++) {
        // dual 1: lam1 = max(lam1 + sig*(S xb) - sig*b, 0)
        float4 acc = make_float4(0.f, 0.f, 0.f, 0.f);
        for (int j = 0; j < rcnt; j++) {
            const int idx = g_csr_idxT[j * MDIM + t];   // coalesced
            acc = f4add(acc, xb_sh[idx]);               // LDS.128 gather
        }
        lam1r.x = fmaxf(lam1r.x + tau * acc.x - tau * b4.x, 0.f);
        lam1r.y = fmaxf(lam1r.y + tau * acc.y - tau * b4.y, 0.f);
        lam1r.z = fmaxf(lam1r.z + tau * acc.z - tau * b4.z, 0.f);
        lam1r.w = fmaxf(lam1r.w + tau * acc.w - tau * b4.w, 0.f);
        lam1_sh[t] = lam1r;

        // dual 2 (elementwise): lam2 = min(lam2 + sig*xb, 0)
        #pragma unroll
        for (int k = 0; k < 4; k++) {
            lam2[k].x = fminf(lam2[k].x + tau * xb[k].x, 0.f);
            lam2[k].y = fminf(lam2[k].y + tau * xb[k].y, 0.f);
            lam2[k].z = fminf(lam2[k].z + tau * xb[k].z, 0.f);
            lam2[k].w = fminf(lam2[k].w + tau * xb[k].w, 0.f);
        }
        __syncthreads();

        // primal: u = x - tau*(S^T lam1 + lam2) + tau - z
        float4 u[4];
        float4 ss = make_float4(0.f, 0.f, 0.f, 0.f);
        #pragma unroll
        for (int k = 0; k < 4; k++) {
            float4 ca = make_float4(0.f, 0.f, 0.f, 0.f);
            const int n = t + 128 * k;
            for (int j = 0; j < cc[k]; j++) {
                const int idx = g_csc_idxT[j * NDIM + n];  // coalesced
                ca = f4add(ca, lam1_sh[idx]);              // LDS.128 gather
            }
            u[k].x = (x[k].x - tau * (ca.x + lam2[k].x)) + tau - z[k].x;
            u[k].y = (x[k].y - tau * (ca.y + lam2[k].y)) + tau - z[k].y;
            u[k].z = (x[k].z - tau * (ca.z + lam2[k].z)) + tau - z[k].z;
            u[k].w = (x[k].w - tau * (ca.w + lam2[k].w)) + tau - z[k].w;
            ss.x += u[k].x * u[k].x;
            ss.y += u[k].y * u[k].y;
            ss.z += u[k].z * u[k].z;
            ss.w += u[k].w * u[k].w;
        }

        // block reduce ||u||^2 per row (4 components) over 128 threads
        #pragma unroll
        for (int o = 16; o > 0; o >>= 1) {
            ss.x += __shfl_xor_sync(0xffffffffu, ss.x, o);
            ss.y += __shfl_xor_sync(0xffffffffu, ss.y, o);
            ss.z += __shfl_xor_sync(0xffffffffu, ss.z, o);
            ss.w += __shfl_xor_sync(0xffffffffu, ss.w, o);
        }
        if ((t & 31) == 0) red[t >> 5] = ss;
        __syncthreads();
        {
            const float4 tot = f4add(f4add(red[0], red[1]), f4add(red[2], red[3]));
            const float tc = tau * CONTROLF;
            float4 sc;
            sc.x = fmaxf(0.f, 1.f - tc / fmaxf(sqrtf(tot.x), 1e-12f));
            sc.y = fmaxf(0.f, 1.f - tc / fmaxf(sqrtf(tot.y), 1e-12f));
            sc.z = fmaxf(0.f, 1.f - tc / fmaxf(sqrtf(tot.z), 1e-12f));
            sc.w = fmaxf(0.f, 1.f - tc / fmaxf(sqrtf(tot.w), 1e-12f));

            #pragma unroll
            for (int k = 0; k < 4; k++) {
                float4 xn;
                xn.x = z[k].x + sc.x * u[k].x;
                xn.y = z[k].y + sc.y * u[k].y;
                xn.z = z[k].z + sc.z * u[k].z;
                xn.w = z[k].w + sc.w * u[k].w;
                float4 nb;
                nb.x = 2.f * xn.x - x[k].x;
                nb.y = 2.f * xn.y - x[k].y;
                nb.z = 2.f * xn.z - x[k].z;
                nb.w = 2.f * xn.w - x[k].w;
                x[k] = xn;
                xb[k] = nb;
                xb_sh[t + 128 * k] = nb;
            }
        }
        __syncthreads();
    }

    #pragma unroll
    for (int k = 0; k < 4; k++) {
        const int n = t + 128 * k;
        out[(row0 + 0) * NDIM + n] = x[k].x;
        out[(row0 + 1) * NDIM + n] = x[k].y;
        out[(row0 + 2) * NDIM + n] = x[k].z;
        out[(row0 + 3) * NDIM + n] = x[k].w;
    }
}

// ---------------------------------------------------------------------------
extern "C" void kernel_launch(void* const* d_in, const int* in_sizes, int n_in,
                              void* d_out, int out_size) {
    const float* X  = (const float*)d_in[0];
    const float* W1 = (const float*)d_in[1];
    const float* B1 = (const float*)d_in[2];
    const float* W2 = (const float*)d_in[3];
    const float* B2 = (const float*)d_in[4];
    const float* W3 = (const float*)d_in[5];
    const float* B3 = (const float*)d_in[6];
    const float* W4 = (const float*)d_in[7];
    const float* B4 = (const float*)d_in[8];
    const float* S  = (const float*)d_in[9];
    const int batch = in_sizes[0] / MDIM;

    prep_kernel<<<1, NDIM>>>(S);
    solve_kernel<<<batch / RROWS, MDIM>>>(X, W1, B1, W2, B2, W3, B3, W4, B4,
                                          (float*)d_out);
}